// round 7
// baseline (speedup 1.0000x reference)
#include <cuda_runtime.h>

typedef unsigned long long u64;
typedef unsigned int u32;

#define NCTA_DIR 64

// ---------------------------------------------------------------------------
// Device scratch (static __device__ arrays — no allocation)
// ---------------------------------------------------------------------------
__device__ float g_h0[2][2][256 * 512];   // [dir][buf][B*H] layer-0 hidden (double buffered)
__device__ float g_h1[2][2][256 * 512];   // layer-1 hidden
__device__ float g_v1[2][256 * 256];      // layer-1 input (= FC0 output)
__device__ u32   g_cnt[2];                // barrier arrival counters (protocol resets to 0)
__device__ u32   g_gen[2];                // barrier generation (monotonic across replays)

// ---------------------------------------------------------------------------
// f32x2 packed-FMA helpers (sm_100+; one FFMA2 = 2 fp32 FMAs)
// ---------------------------------------------------------------------------
__device__ __forceinline__ u64 pk2(float x, float y) {
    u64 r; asm("mov.b64 %0, {%1, %2};" : "=l"(r) : "f"(x), "f"(y)); return r;
}
__device__ __forceinline__ void upk2(u64 v, float& x, float& y) {
    asm("mov.b64 {%0, %1}, %2;" : "=f"(x), "=f"(y) : "l"(v));
}
__device__ __forceinline__ void fma2(u64& d, u64 a, u64 b) {
    asm("fma.rn.f32x2 %0, %1, %2, %0;" : "+l"(d) : "l"(a), "l"(b));
}

__device__ __forceinline__ float sigmf(float x) {
    return __fdividef(1.0f, 1.0f + __expf(-x));
}
__device__ __forceinline__ float tanhft(float x) {
    // 1 - 2/(1+exp(2x)); saturates correctly at +/-1 (2/inf -> 0)
    return 1.0f - __fdividef(2.0f, 1.0f + __expf(2.0f * x));
}

// ---------------------------------------------------------------------------
// Per-direction grid barrier over 64 co-resident CTAs.
// Each thread fences (gpu scope -> orders writes AND invalidates L1D), then
// CTA-syncs, then thread 0 arrives / spins on the generation counter.
// ---------------------------------------------------------------------------
__device__ __forceinline__ void dbar(int dir) {
    __threadfence();
    __syncthreads();
    if (threadIdx.x == 0) {
        volatile u32* gv = &g_gen[dir];
        u32 old = *gv;                      // read BEFORE arriving
        if (atomicAdd(&g_cnt[dir], 1u) == NCTA_DIR - 1) {
            atomicExch(&g_cnt[dir], 0u);
            __threadfence();
            atomicAdd(&g_gen[dir], 1u);
        } else {
            while (*gv == old) { __nanosleep(64); }
        }
    }
    __syncthreads();
}

// ---------------------------------------------------------------------------
// smem staging helpers
//   sA: duplicated A packs, row k (stride 132 floats), entry r at float 2r = (a,a)
//   sW: weights, row k (stride 132 floats), col j = unit*4 + gate
// ---------------------------------------------------------------------------
__device__ __forceinline__ void stdup(float* s, int kq, int r8, float4 v) {
    *(float2*)(s + (kq * 4 + 0) * 132 + 2 * r8) = make_float2(v.x, v.x);
    *(float2*)(s + (kq * 4 + 1) * 132 + 2 * r8) = make_float2(v.y, v.y);
    *(float2*)(s + (kq * 4 + 2) * 132 + 2 * r8) = make_float2(v.z, v.z);
    *(float2*)(s + (kq * 4 + 3) * 132 + 2 * r8) = make_float2(v.w, v.w);
}

// ---------------------------------------------------------------------------
// Fused gate-GEMM + LSTM cell tile: 64 batch x (32 units x 4 gates), K<=768.
// warp w -> batch rows w*8..w*8+7 ; lane l -> unit l, all 4 gates.
// c state stays in registers (cst[8]).
// ---------------------------------------------------------------------------
__device__ __forceinline__ void gate_tile(
    const float* __restrict__ vin, int vstride,
    const float* __restrict__ hprev,
    const float* __restrict__ wih,   // [2048,256]
    const float* __restrict__ whh,   // [2048,512]
    u64 b01, u64 b23,
    float* __restrict__ hout,
    float* cst,
    int btile, int utile, int nchunks,
    float* sA, float* sW)
{
    const int tid = threadIdx.x, lane = tid & 31, wrp = tid >> 5;

    u64 a01[8], a23[8];
#pragma unroll
    for (int i = 0; i < 8; ++i) { a01[i] = b01; a23[i] = b23; }

    float4 pa[2], pw[4];

    auto ldA = [&](int c) {
        int kc = c * 32;
        const float* base; int str;
        if (c < 8) { base = vin + kc;             str = vstride; }
        else       { base = hprev + (kc - 256);   str = 512;     }
#pragma unroll
        for (int q = 0; q < 2; ++q) {
            int idx = tid + q * 256, r8 = idx >> 3, kq = idx & 7;
            pa[q] = __ldcg((const float4*)(base + (btile * 64 + r8) * str + kq * 4));
        }
    };
    auto ldW = [&](int c) {
        int kc = c * 32;
#pragma unroll
        for (int q = 0; q < 4; ++q) {
            int idx = tid + q * 256, j = idx >> 3, kq = idx & 7;
            int n = (j & 3) * 512 + utile * 32 + (j >> 2);
            const float* p = (c < 8) ? (wih + n * 256 + kc + kq * 4)
                                     : (whh + n * 512 + (kc - 256) + kq * 4);
            pw[q] = *(const float4*)p;
        }
    };
    auto stg = [&]() {
#pragma unroll
        for (int q = 0; q < 2; ++q) {
            int idx = tid + q * 256;
            stdup(sA, idx & 7, idx >> 3, pa[q]);
        }
#pragma unroll
        for (int q = 0; q < 4; ++q) {
            int idx = tid + q * 256, j = idx >> 3, kq = idx & 7;
            sW[(kq * 4 + 0) * 132 + j] = pw[q].x;
            sW[(kq * 4 + 1) * 132 + j] = pw[q].y;
            sW[(kq * 4 + 2) * 132 + j] = pw[q].z;
            sW[(kq * 4 + 3) * 132 + j] = pw[q].w;
        }
    };

    ldA(0); ldW(0);
#pragma unroll 1
    for (int c = 0; c < nchunks; ++c) {
        __syncthreads();
        stg();
        __syncthreads();
        if (c + 1 < nchunks) { ldA(c + 1); ldW(c + 1); }
#pragma unroll
        for (int k = 0; k < 32; ++k) {
            ulonglong2 w = *(const ulonglong2*)(sW + k * 132 + lane * 4);
#pragma unroll
            for (int i = 0; i < 4; ++i) {
                ulonglong2 ap = *(const ulonglong2*)(sA + k * 132 + wrp * 16 + i * 4);
                fma2(a01[2 * i],     ap.x, w.x);
                fma2(a23[2 * i],     ap.x, w.y);
                fma2(a01[2 * i + 1], ap.y, w.x);
                fma2(a23[2 * i + 1], ap.y, w.y);
            }
        }
    }

    // LSTM cell update (gate order i, f, g, o)
    const int u  = utile * 32 + lane;
    const int rb = btile * 64 + wrp * 8;
#pragma unroll
    for (int rr = 0; rr < 8; ++rr) {
        float gi, gf, gg, go;
        upk2(a01[rr], gi, gf);
        upk2(a23[rr], gg, go);
        float cc = sigmf(gf) * cst[rr] + sigmf(gi) * tanhft(gg);
        cst[rr] = cc;
        hout[(rb + rr) * 512 + u] = sigmf(go) * tanhft(cc);
    }
}

// ---------------------------------------------------------------------------
// FC tile: 64 batch x 32 cols, K = 512.  out = hin @ wfc^T + bfc
// thread: colpair cp = tid&15 (cols 2cp,2cp+1), rowgroup rg = tid>>4 (4 rows)
// ---------------------------------------------------------------------------
__device__ __forceinline__ void fc_tile(
    const float* __restrict__ hin,   // [256,512]
    const float* __restrict__ wfc,   // [256,512]
    const float* __restrict__ bfc,
    float* __restrict__ outp, int ostride,
    int fb, int fv,
    float* sH, float* sWf)
{
    const int tid = threadIdx.x, cp = tid & 15, rg = tid >> 4;
    const int c0 = fv * 32 + 2 * cp;

    u64 acc[4];
    u64 bb = pk2(bfc[c0], bfc[c0 + 1]);
#pragma unroll
    for (int i = 0; i < 4; ++i) acc[i] = bb;

    float4 ph[2], pwf;
    auto ld = [&](int c) {
        int kc = c * 32;
#pragma unroll
        for (int q = 0; q < 2; ++q) {
            int idx = tid + q * 256, r8 = idx >> 3, kq = idx & 7;
            ph[q] = __ldcg((const float4*)(hin + (fb * 64 + r8) * 512 + kc + kq * 4));
        }
        int vv = tid >> 3, kq = tid & 7;
        pwf = *(const float4*)(wfc + (fv * 32 + vv) * 512 + kc + kq * 4);
    };
    auto stg = [&]() {
#pragma unroll
        for (int q = 0; q < 2; ++q) {
            int idx = tid + q * 256;
            stdup(sH, idx & 7, idx >> 3, ph[q]);
        }
        int vv = tid >> 3, kq = tid & 7;
        sWf[(kq * 4 + 0) * 34 + vv] = pwf.x;
        sWf[(kq * 4 + 1) * 34 + vv] = pwf.y;
        sWf[(kq * 4 + 2) * 34 + vv] = pwf.z;
        sWf[(kq * 4 + 3) * 34 + vv] = pwf.w;
    };

    ld(0);
#pragma unroll 1
    for (int c = 0; c < 16; ++c) {
        __syncthreads();
        stg();
        __syncthreads();
        if (c + 1 < 16) ld(c + 1);
#pragma unroll
        for (int k = 0; k < 32; ++k) {
            u64 w = *(const u64*)(sWf + k * 34 + 2 * cp);
            ulonglong2 a0 = *(const ulonglong2*)(sH + k * 132 + rg * 8);
            ulonglong2 a1 = *(const ulonglong2*)(sH + k * 132 + rg * 8 + 4);
            fma2(acc[0], a0.x, w);
            fma2(acc[1], a0.y, w);
            fma2(acc[2], a1.x, w);
            fma2(acc[3], a1.y, w);
        }
    }

#pragma unroll
    for (int i = 0; i < 4; ++i) {
        float o0, o1;
        upk2(acc[i], o0, o1);
        int rr = fb * 64 + rg * 4 + i;
        outp[rr * ostride + c0]     = o0;
        outp[rr * ostride + c0 + 1] = o1;
    }
}

// ---------------------------------------------------------------------------
// Persistent kernel: 128 CTAs (64/direction), 512 barriers/direction.
// Phase A(t): L0-gates(t) [CTAs 0-31] || L1-gates(t-1) [CTAs 32-63]
// Phase B(t): FC0(t)                 || FC1(t-1) -> d_out
// ---------------------------------------------------------------------------
__global__ void __launch_bounds__(256, 1)
bilstm_kernel(const float* __restrict__ x,
              const float* __restrict__ wih_l, const float* __restrict__ whh_l,
              const float* __restrict__ bih_l, const float* __restrict__ bhh_l,
              const float* __restrict__ wfc_l, const float* __restrict__ bfc_l,
              const float* __restrict__ wih_r, const float* __restrict__ whh_r,
              const float* __restrict__ bih_r, const float* __restrict__ bhh_r,
              const float* __restrict__ wfc_r, const float* __restrict__ bfc_r,
              float* __restrict__ out)
{
    __shared__ __align__(16) float smem[8448];
    float* sA = smem;
    float* sW = smem + 4224;

    const int dir  = (int)(blockIdx.x >> 6);
    const int r    = (int)(blockIdx.x & 63);
    const int lane = threadIdx.x & 31;

    const float* wih = dir ? wih_r : wih_l;
    const float* whh = dir ? whh_r : whh_l;
    const float* bih = dir ? bih_r : bih_l;
    const float* bhh = dir ? bhh_r : bhh_l;
    const float* wfc = dir ? wfc_r : wfc_l;
    const float* bfc = dir ? bfc_r : bfc_l;

    const bool isL0  = (r < 32);
    const int  gr    = isL0 ? r : (r - 32);
    const int  layer = isL0 ? 0 : 1;

    int bt[2], ut[2];
#pragma unroll
    for (int p = 0; p < 2; ++p) { int m = 2 * gr + p; bt[p] = m >> 4; ut[p] = m & 15; }

    const float* gwih = wih + layer * 2048 * 256;
    const float* gwhh = whh + layer * 2048 * 512;
    const float* lbih = bih + layer * 2048;
    const float* lbhh = bhh + layer * 2048;
    const float* fwfc = wfc + layer * 256 * 512;
    const float* fbfc = bfc + layer * 256;

    u64 gb01[2], gb23[2];
#pragma unroll
    for (int p = 0; p < 2; ++p) {
        int u = ut[p] * 32 + lane;
        gb01[p] = pk2(lbih[u]        + lbhh[u],        lbih[512 + u]  + lbhh[512 + u]);
        gb23[p] = pk2(lbih[1024 + u] + lbhh[1024 + u], lbih[1536 + u] + lbhh[1536 + u]);
    }
    const int fb = gr >> 3, fv = gr & 7;

    float cst[2][8];
#pragma unroll
    for (int p = 0; p < 2; ++p)
#pragma unroll
        for (int i = 0; i < 8; ++i) cst[p][i] = 0.0f;

#pragma unroll 1
    for (int t = 0; t <= 255; ++t) {
        // ---------------- Phase A: gate GEMMs + cell ----------------
        bool doG; const float* vin; int vs, nch; const float* hp; float* ho;
        if (isL0) {
            doG = (t < 255);
            int xc = dir ? (255 - t) : t;
            vin = x + xc * 256;  vs = 65536;
            nch = (t == 0) ? 8 : 24;
            hp = g_h0[dir][(t + 1) & 1];
            ho = g_h0[dir][t & 1];
        } else {
            int s = t - 1;
            doG = (s >= 0);
            vin = g_v1[dir];  vs = 256;
            nch = (s <= 0) ? 8 : 24;
            hp = g_h1[dir][(s + 1) & 1];
            ho = g_h1[dir][s & 1];
        }
        if (doG) {
#pragma unroll
            for (int p = 0; p < 2; ++p)
                gate_tile(vin, vs, hp, gwih, gwhh, gb01[p], gb23[p],
                          ho, cst[p], bt[p], ut[p], nch, sA, sW);
        }
        dbar(dir);

        // ---------------- Phase B: FC layers ----------------
        bool doF; const float* hin; float* op; int os;
        if (isL0) {
            doF = (t < 255);
            hin = g_h0[dir][t & 1];
            op  = g_v1[dir];  os = 256;
        } else {
            int s = t - 1;
            doF = (s >= 0);
            hin = g_h1[dir][s & 1];
            int tcol = dir ? (255 + s) : s;
            op  = out + tcol * 256;  os = 510 * 256;
        }
        if (doF) fc_tile(hin, fwfc, fbfc, op, os, fb, fv, sA, sW);
        dbar(dir);
    }
}

extern "C" void kernel_launch(void* const* d_in, const int* in_sizes, int n_in,
                              void* d_out, int out_size)
{
    (void)in_sizes; (void)n_in; (void)out_size;
    bilstm_kernel<<<128, 256>>>(
        (const float*)d_in[0],
        (const float*)d_in[1],  (const float*)d_in[2],  (const float*)d_in[3],
        (const float*)d_in[4],  (const float*)d_in[5],  (const float*)d_in[6],
        (const float*)d_in[7],  (const float*)d_in[8],  (const float*)d_in[9],
        (const float*)d_in[10], (const float*)d_in[11], (const float*)d_in[12],
        (float*)d_out);
}

// round 9
// speedup vs baseline: 1.2346x; 1.2346x over previous
#include <cuda_runtime.h>

typedef unsigned long long u64;
typedef unsigned int u32;

#define NCTA_DIR 64

// ---------------------------------------------------------------------------
// Device scratch (static __device__ arrays — no allocation)
// ---------------------------------------------------------------------------
__device__ float g_h0[2][2][256 * 512];   // [dir][buf][B*H] layer-0 hidden (double buffered)
__device__ float g_h1[2][2][256 * 512];   // layer-1 hidden
__device__ float g_v1[2][256 * 256];      // layer-1 input (= FC0 output)
__device__ u32   g_cnt[2];                // barrier arrival counters
__device__ u32   g_gen[2];                // barrier generation (monotonic across replays)

// ---------------------------------------------------------------------------
// f32x2 packed-FMA helpers
// ---------------------------------------------------------------------------
__device__ __forceinline__ u64 pk2(float x, float y) {
    u64 r; asm("mov.b64 %0, {%1, %2};" : "=l"(r) : "f"(x), "f"(y)); return r;
}
__device__ __forceinline__ float sumhalves(u64 v) {
    float x, y; asm("mov.b64 {%0, %1}, %2;" : "=f"(x), "=f"(y) : "l"(v));
    return x + y;
}
__device__ __forceinline__ void fma2(u64& d, u64 a, u64 b) {
    asm("fma.rn.f32x2 %0, %1, %2, %0;" : "+l"(d) : "l"(a), "l"(b));
}

__device__ __forceinline__ float tanhap(float x) {
    float y; asm("tanh.approx.f32 %0, %1;" : "=f"(y) : "f"(x)); return y;
}
__device__ __forceinline__ float sigmf(float x) {
    return fmaf(0.5f, tanhap(0.5f * x), 0.5f);
}

// ---------------------------------------------------------------------------
// Per-direction grid barrier over 64 co-resident CTAs (sense via generation).
// ---------------------------------------------------------------------------
__device__ __forceinline__ void dbar(int dir) {
    __threadfence();
    __syncthreads();
    if (threadIdx.x == 0) {
        volatile u32* gv = &g_gen[dir];
        u32 old = *gv;                      // read BEFORE arriving
        if (atomicAdd(&g_cnt[dir], 1u) == NCTA_DIR - 1) {
            atomicExch(&g_cnt[dir], 0u);
            __threadfence();
            atomicAdd(&g_gen[dir], 1u);
        } else {
            while (*gv == old) { __nanosleep(64); }
        }
    }
    __syncthreads();
}

// ---------------------------------------------------------------------------
// smem layout (per chunk of 32 k-values), all rows stride 36 floats (144 B):
//   - 16B-aligned for LDS.128 / STS.128 (k offsets are multiples of 4 floats)
//   - inter-lane stride for W reads = 1 row = 144 B; 144/16 = 9 (odd mod 8)
//     -> the 8 lanes of each wavefront hit 8 distinct 16B quads: conflict-free
//   sA[64 rows][k]             (A reads are warp-uniform broadcasts)
//   sW[128 rows][k], row = gate*32 + unit_local
// ---------------------------------------------------------------------------

// Fused gate-GEMM + LSTM cell tile: 64 batch x (32 units x 4 gates), K = nchunks*32.
// warp w -> batch rows w*8..w*8+7 ; lane l -> unit l, all 4 gates.
__device__ __forceinline__ void gate_tile(
    const float* __restrict__ vin, int vstride,
    const float* __restrict__ hprev,
    const float* __restrict__ wih,   // [2048,256]
    const float* __restrict__ whh,   // [2048,512]
    float bi, float bf, float bg, float bo,
    float* __restrict__ hout,
    float* cst,
    int btile, int utile, int nchunks,
    float* sA, float* sW)
{
    const int tid = threadIdx.x, lane = tid & 31, wrp = tid >> 5;

    u64 acc[8][4];
    {
        u64 b0 = pk2(bi, 0.0f), b1 = pk2(bf, 0.0f), b2 = pk2(bg, 0.0f), b3 = pk2(bo, 0.0f);
#pragma unroll
        for (int r = 0; r < 8; ++r) {
            acc[r][0] = b0; acc[r][1] = b1; acc[r][2] = b2; acc[r][3] = b3;
        }
    }

    float4 pa[2], pw[4];

    auto ldA = [&](int c) {
        int kc = c * 32;
        const float* base; int str;
        if (c < 8) { base = vin + kc;           str = vstride; }
        else       { base = hprev + (kc - 256); str = 512;     }
#pragma unroll
        for (int q = 0; q < 2; ++q) {
            int idx = tid + q * 256, r8 = idx >> 3, kq = idx & 7;
            pa[q] = __ldcg((const float4*)(base + (btile * 64 + r8) * str + kq * 4));
        }
    };
    auto ldW = [&](int c) {
        int kc = c * 32;
#pragma unroll
        for (int q = 0; q < 4; ++q) {
            int idx = tid + q * 256, j = idx >> 3, kq = idx & 7;
            // row j = gate*32 + unit_local  ->  weight row n = gate*512 + utile*32 + unit
            int n = (j >> 5) * 512 + utile * 32 + (j & 31);
            const float* p = (c < 8) ? (wih + n * 256 + kc + kq * 4)
                                     : (whh + n * 512 + (kc - 256) + kq * 4);
            pw[q] = *(const float4*)p;
        }
    };
    auto stg = [&]() {
#pragma unroll
        for (int q = 0; q < 2; ++q) {
            int idx = tid + q * 256, r8 = idx >> 3, kq = idx & 7;
            *(float4*)(sA + r8 * 36 + kq * 4) = pa[q];     // aligned STS.128
        }
#pragma unroll
        for (int q = 0; q < 4; ++q) {
            int idx = tid + q * 256, j = idx >> 3, kq = idx & 7;
            *(float4*)(sW + j * 36 + kq * 4) = pw[q];      // aligned STS.128
        }
    };

    ldA(0); ldW(0);
#pragma unroll 1
    for (int c = 0; c < nchunks; ++c) {
        __syncthreads();
        stg();
        __syncthreads();
        if (c + 1 < nchunks) { ldA(c + 1); ldW(c + 1); }
#pragma unroll
        for (int kq4 = 0; kq4 < 8; ++kq4) {
            const int k = kq4 * 4;
            ulonglong2 w0 = *(const ulonglong2*)(sW + (lane      ) * 36 + k);
            ulonglong2 w1 = *(const ulonglong2*)(sW + (lane +  32) * 36 + k);
            ulonglong2 w2 = *(const ulonglong2*)(sW + (lane +  64) * 36 + k);
            ulonglong2 w3 = *(const ulonglong2*)(sW + (lane +  96) * 36 + k);
#pragma unroll
            for (int r = 0; r < 8; ++r) {
                ulonglong2 a = *(const ulonglong2*)(sA + (wrp * 8 + r) * 36 + k);
                fma2(acc[r][0], a.x, w0.x); fma2(acc[r][0], a.y, w0.y);
                fma2(acc[r][1], a.x, w1.x); fma2(acc[r][1], a.y, w1.y);
                fma2(acc[r][2], a.x, w2.x); fma2(acc[r][2], a.y, w2.y);
                fma2(acc[r][3], a.x, w3.x); fma2(acc[r][3], a.y, w3.y);
            }
        }
    }

    // LSTM cell update (gate order i, f, g, o); c stays in registers
    const int u  = utile * 32 + lane;
    const int rb = btile * 64 + wrp * 8;
#pragma unroll
    for (int rr = 0; rr < 8; ++rr) {
        float gi = sumhalves(acc[rr][0]);
        float gf = sumhalves(acc[rr][1]);
        float gg = sumhalves(acc[rr][2]);
        float go = sumhalves(acc[rr][3]);
        float cc = sigmf(gf) * cst[rr] + sigmf(gi) * tanhap(gg);
        cst[rr] = cc;
        hout[(rb + rr) * 512 + u] = sigmf(go) * tanhap(cc);
    }
}

// ---------------------------------------------------------------------------
// FC tile: 64 batch x 32 cols, K = 512.  out = hin @ wfc^T + bfc
// warp w -> rows w*8..w*8+7 ; lane -> column.
//   sWf[32 cols][k] stride 36 (aligned; inter-lane 144 B -> conflict-free)
// ---------------------------------------------------------------------------
__device__ __forceinline__ void fc_tile(
    const float* __restrict__ hin,   // [256,512]
    const float* __restrict__ wfc,   // [256,512]
    const float* __restrict__ bfc,
    float* __restrict__ outp, int ostride,
    int fb, int fv,
    float* sA, float* sWf)
{
    const int tid = threadIdx.x, lane = tid & 31, wrp = tid >> 5;
    const int c0 = fv * 32 + lane;

    u64 acc[8];
    {
        u64 bb = pk2(bfc[c0], 0.0f);
#pragma unroll
        for (int r = 0; r < 8; ++r) acc[r] = bb;
    }

    float4 ph[2], pwf;
    auto ld = [&](int c) {
        int kc = c * 32;
#pragma unroll
        for (int q = 0; q < 2; ++q) {
            int idx = tid + q * 256, r8 = idx >> 3, kq = idx & 7;
            ph[q] = __ldcg((const float4*)(hin + (fb * 64 + r8) * 512 + kc + kq * 4));
        }
        int vv = tid >> 3, kq = tid & 7;
        pwf = *(const float4*)(wfc + (fv * 32 + vv) * 512 + kc + kq * 4);
    };
    auto stg = [&]() {
#pragma unroll
        for (int q = 0; q < 2; ++q) {
            int idx = tid + q * 256, r8 = idx >> 3, kq = idx & 7;
            *(float4*)(sA + r8 * 36 + kq * 4) = ph[q];
        }
        int vv = tid >> 3, kq = tid & 7;
        *(float4*)(sWf + vv * 36 + kq * 4) = pwf;
    };

    ld(0);
#pragma unroll 1
    for (int c = 0; c < 16; ++c) {
        __syncthreads();
        stg();
        __syncthreads();
        if (c + 1 < 16) ld(c + 1);
#pragma unroll
        for (int kq4 = 0; kq4 < 8; ++kq4) {
            const int k = kq4 * 4;
            ulonglong2 w = *(const ulonglong2*)(sWf + lane * 36 + k);
#pragma unroll
            for (int r = 0; r < 8; ++r) {
                ulonglong2 a = *(const ulonglong2*)(sA + (wrp * 8 + r) * 36 + k);
                fma2(acc[r], a.x, w.x);
                fma2(acc[r], a.y, w.y);
            }
        }
    }

#pragma unroll
    for (int r = 0; r < 8; ++r) {
        int rr = fb * 64 + wrp * 8 + r;
        outp[rr * ostride + c0] = sumhalves(acc[r]);
    }
}

// ---------------------------------------------------------------------------
// Persistent kernel: 128 CTAs (64/direction), 512 barriers/direction.
// Phase A(t): L0-gates(t) [CTAs 0-31] || L1-gates(t-1) [CTAs 32-63]
// Phase B(t): FC0(t)                 || FC1(t-1) -> d_out
// ---------------------------------------------------------------------------
__global__ void __launch_bounds__(256, 1)
bilstm_kernel(const float* __restrict__ x,
              const float* __restrict__ wih_l, const float* __restrict__ whh_l,
              const float* __restrict__ bih_l, const float* __restrict__ bhh_l,
              const float* __restrict__ wfc_l, const float* __restrict__ bfc_l,
              const float* __restrict__ wih_r, const float* __restrict__ whh_r,
              const float* __restrict__ bih_r, const float* __restrict__ bhh_r,
              const float* __restrict__ wfc_r, const float* __restrict__ bfc_r,
              float* __restrict__ out)
{
    __shared__ __align__(16) float smem[2304 + 4608];
    float* sA = smem;              // 64*36  = 2304 floats
    float* sW = smem + 2304;       // 128*36 = 4608 floats (FC uses first 32*36)

    const int dir  = (int)(blockIdx.x >> 6);
    const int r    = (int)(blockIdx.x & 63);
    const int lane = threadIdx.x & 31;

    const float* wih = dir ? wih_r : wih_l;
    const float* whh = dir ? whh_r : whh_l;
    const float* bih = dir ? bih_r : bih_l;
    const float* bhh = dir ? bhh_r : bhh_l;
    const float* wfc = dir ? wfc_r : wfc_l;
    const float* bfc = dir ? bfc_r : bfc_l;

    const bool isL0  = (r < 32);
    const int  gr    = isL0 ? r : (r - 32);
    const int  layer = isL0 ? 0 : 1;

    int bt[2], ut[2];
#pragma unroll
    for (int p = 0; p < 2; ++p) { int m = 2 * gr + p; bt[p] = m >> 4; ut[p] = m & 15; }

    const float* gwih = wih + layer * 2048 * 256;
    const float* gwhh = whh + layer * 2048 * 512;
    const float* lbih = bih + layer * 2048;
    const float* lbhh = bhh + layer * 2048;
    const float* fwfc = wfc + layer * 256 * 512;
    const float* fbfc = bfc + layer * 256;

    float gb[2][4];
#pragma unroll
    for (int p = 0; p < 2; ++p) {
        int u = ut[p] * 32 + lane;
        gb[p][0] = lbih[u]        + lbhh[u];
        gb[p][1] = lbih[512 + u]  + lbhh[512 + u];
        gb[p][2] = lbih[1024 + u] + lbhh[1024 + u];
        gb[p][3] = lbih[1536 + u] + lbhh[1536 + u];
    }
    const int fb = gr >> 3, fv = gr & 7;

    float cst[2][8];
#pragma unroll
    for (int p = 0; p < 2; ++p)
#pragma unroll
        for (int i = 0; i < 8; ++i) cst[p][i] = 0.0f;

#pragma unroll 1
    for (int t = 0; t <= 255; ++t) {
        // ---------------- Phase A: gate GEMMs + cell ----------------
        bool doG; const float* vin; int vs, nch; const float* hp; float* ho;
        if (isL0) {
            doG = (t < 255);
            int xc = dir ? (255 - t) : t;
            vin = x + xc * 256;  vs = 65536;
            nch = (t == 0) ? 8 : 24;
            hp = g_h0[dir][(t + 1) & 1];
            ho = g_h0[dir][t & 1];
        } else {
            int s = t - 1;
            doG = (s >= 0);
            vin = g_v1[dir];  vs = 256;
            nch = (s <= 0) ? 8 : 24;
            hp = g_h1[dir][(s + 1) & 1];
            ho = g_h1[dir][s & 1];
        }
        if (doG) {
#pragma unroll 1
            for (int p = 0; p < 2; ++p)
                gate_tile(vin, vs, hp, gwih, gwhh,
                          gb[p][0], gb[p][1], gb[p][2], gb[p][3],
                          ho, cst[p], bt[p], ut[p], nch, sA, sW);
        }
        dbar(dir);

        // ---------------- Phase B: FC layers ----------------
        bool doF; const float* hin; float* op; int os;
        if (isL0) {
            doF = (t < 255);
            hin = g_h0[dir][t & 1];
            op  = g_v1[dir];  os = 256;
        } else {
            int s = t - 1;
            doF = (s >= 0);
            hin = g_h1[dir][s & 1];
            int tcol = dir ? (255 + s) : s;
            op  = out + tcol * 256;  os = 510 * 256;
        }
        if (doF) fc_tile(hin, fwfc, fbfc, op, os, fb, fv, sA, sW);
        dbar(dir);
    }
}

extern "C" void kernel_launch(void* const* d_in, const int* in_sizes, int n_in,
                              void* d_out, int out_size)
{
    (void)in_sizes; (void)n_in; (void)out_size;
    bilstm_kernel<<<128, 256>>>(
        (const float*)d_in[0],
        (const float*)d_in[1],  (const float*)d_in[2],  (const float*)d_in[3],
        (const float*)d_in[4],  (const float*)d_in[5],  (const float*)d_in[6],
        (const float*)d_in[7],  (const float*)d_in[8],  (const float*)d_in[9],
        (const float*)d_in[10], (const float*)d_in[11], (const float*)d_in[12],
        (float*)d_out);
}

// round 10
// speedup vs baseline: 1.2519x; 1.0139x over previous
#include <cuda_runtime.h>

typedef unsigned long long u64;
typedef unsigned int u32;

#define NCTA_DIR 64
#define CHUNK_F  6912          // floats per smem chunk buffer: sA 64*36 + sW 128*36
#define SMEM_BYTES (2 * CHUNK_F * 4)

// ---------------------------------------------------------------------------
// Device scratch (static __device__ arrays — no allocation)
// ---------------------------------------------------------------------------
__device__ float g_h0[2][2][256 * 512];   // [dir][buf][B*H] layer-0 hidden (double buffered)
__device__ float g_h1[2][2][256 * 512];   // layer-1 hidden
__device__ float g_v1[2][256 * 256];      // layer-1 input (= FC0 output)
__device__ u32   g_cnt[2];                // barrier arrival counters
__device__ u32   g_gen[2];                // barrier generation (monotonic across replays)

// ---------------------------------------------------------------------------
// f32x2 packed-FMA helpers
// ---------------------------------------------------------------------------
__device__ __forceinline__ u64 pk2(float x, float y) {
    u64 r; asm("mov.b64 %0, {%1, %2};" : "=l"(r) : "f"(x), "f"(y)); return r;
}
__device__ __forceinline__ float sumhalves(u64 v) {
    float x, y; asm("mov.b64 {%0, %1}, %2;" : "=f"(x), "=f"(y) : "l"(v));
    return x + y;
}
__device__ __forceinline__ void fma2(u64& d, u64 a, u64 b) {
    asm("fma.rn.f32x2 %0, %1, %2, %0;" : "+l"(d) : "l"(a), "l"(b));
}

__device__ __forceinline__ float tanhap(float x) {
    float y; asm("tanh.approx.f32 %0, %1;" : "=f"(y) : "f"(x)); return y;
}
__device__ __forceinline__ float sigmf(float x) {
    return fmaf(0.5f, tanhap(0.5f * x), 0.5f);
}

// ---------------------------------------------------------------------------
// Per-direction grid barrier over 64 co-resident CTAs.
// Fences only in thread 0: __syncthreads() (CTA-scope fence) + cumulative
// gpu-scope fence in the arriving thread orders ALL threads' prior writes.
// ---------------------------------------------------------------------------
__device__ __forceinline__ void dbar(int dir) {
    __syncthreads();
    if (threadIdx.x == 0) {
        __threadfence();                     // release (cumulative)
        volatile u32* gv = &g_gen[dir];
        u32 old = *gv;                       // read BEFORE arriving
        if (atomicAdd(&g_cnt[dir], 1u) == NCTA_DIR - 1) {
            atomicExch(&g_cnt[dir], 0u);
            __threadfence();
            atomicAdd(&g_gen[dir], 1u);
        } else {
            while (*gv == old) { __nanosleep(32); }
        }
        __threadfence();                     // acquire
    }
    __syncthreads();
}

// ---------------------------------------------------------------------------
// smem chunk layout (per 32 k-values), rows stride 36 floats (144 B):
//   16B-aligned LDS/STS.128; inter-lane stride 144 B -> 9 quads (odd) -> no
//   bank conflicts.  sA[64 rows][k] ; sW[128 rows][k], row = gate*32 + unit.
// Two chunk buffers (double buffered): base + (c&1)*CHUNK_F.
// ---------------------------------------------------------------------------

// Fused gate-GEMM + LSTM cell tile: 64 batch x (32 units x 4 gates), K = nchunks*32.
// warp w -> batch rows w*8..w*8+7 ; lane l -> unit l, all 4 gates.
__device__ __forceinline__ void gate_tile(
    const float* __restrict__ vin, int vstride,
    const float* __restrict__ hprev,
    const float* __restrict__ wih,   // [2048,256]
    const float* __restrict__ whh,   // [2048,512]
    float bi, float bf, float bg, float bo,
    float* __restrict__ hout,
    float* cst,
    int btile, int utile, int nchunks,
    float* smbase)
{
    const int tid = threadIdx.x, lane = tid & 31, wrp = tid >> 5;

    u64 acc[8][4];
    {
        u64 b0 = pk2(bi, 0.0f), b1 = pk2(bf, 0.0f), b2 = pk2(bg, 0.0f), b3 = pk2(bo, 0.0f);
#pragma unroll
        for (int r = 0; r < 8; ++r) {
            acc[r][0] = b0; acc[r][1] = b1; acc[r][2] = b2; acc[r][3] = b3;
        }
    }

    float4 pa[2], pw[4];

    auto ldA = [&](int c) {
        int kc = c * 32;
        const float* base; int str;
        if (c < 8) { base = vin + kc;           str = vstride; }
        else       { base = hprev + (kc - 256); str = 512;     }
#pragma unroll
        for (int q = 0; q < 2; ++q) {
            int idx = tid + q * 256, r8 = idx >> 3, kq = idx & 7;
            pa[q] = __ldcg((const float4*)(base + (btile * 64 + r8) * str + kq * 4));
        }
    };
    auto ldW = [&](int c) {
        int kc = c * 32;
#pragma unroll
        for (int q = 0; q < 4; ++q) {
            int idx = tid + q * 256, j = idx >> 3, kq = idx & 7;
            // row j = gate*32 + unit_local -> weight row n = gate*512 + utile*32 + unit
            int n = (j >> 5) * 512 + utile * 32 + (j & 31);
            const float* p = (c < 8) ? (wih + n * 256 + kc + kq * 4)
                                     : (whh + n * 512 + (kc - 256) + kq * 4);
            pw[q] = __ldcg((const float4*)p);
        }
    };
    auto stg = [&](float* buf) {
        float* sA = buf;
        float* sW = buf + 2304;
#pragma unroll
        for (int q = 0; q < 2; ++q) {
            int idx = tid + q * 256, r8 = idx >> 3, kq = idx & 7;
            *(float4*)(sA + r8 * 36 + kq * 4) = pa[q];
        }
#pragma unroll
        for (int q = 0; q < 4; ++q) {
            int idx = tid + q * 256, j = idx >> 3, kq = idx & 7;
            *(float4*)(sW + j * 36 + kq * 4) = pw[q];
        }
    };

    // Prologue: stage chunk 0 into buffer 0
    ldA(0); ldW(0);
    stg(smbase);
    __syncthreads();

#pragma unroll 1
    for (int c = 0; c < nchunks; ++c) {
        const bool more = (c + 1 < nchunks);
        if (more) { ldA(c + 1); ldW(c + 1); }    // prefetch (hidden under compute)

        float* sA = smbase + (c & 1) * CHUNK_F;
        float* sW = sA + 2304;
#pragma unroll
        for (int kq4 = 0; kq4 < 8; ++kq4) {
            const int k = kq4 * 4;
            ulonglong2 w0 = *(const ulonglong2*)(sW + (lane      ) * 36 + k);
            ulonglong2 w1 = *(const ulonglong2*)(sW + (lane +  32) * 36 + k);
            ulonglong2 w2 = *(const ulonglong2*)(sW + (lane +  64) * 36 + k);
            ulonglong2 w3 = *(const ulonglong2*)(sW + (lane +  96) * 36 + k);
#pragma unroll
            for (int r = 0; r < 8; ++r) {
                ulonglong2 a = *(const ulonglong2*)(sA + (wrp * 8 + r) * 36 + k);
                fma2(acc[r][0], a.x, w0.x); fma2(acc[r][0], a.y, w0.y);
                fma2(acc[r][1], a.x, w1.x); fma2(acc[r][1], a.y, w1.y);
                fma2(acc[r][2], a.x, w2.x); fma2(acc[r][2], a.y, w2.y);
                fma2(acc[r][3], a.x, w3.x); fma2(acc[r][3], a.y, w3.y);
            }
        }

        if (more) {
            stg(smbase + ((c + 1) & 1) * CHUNK_F);   // other buffer: no read/write hazard
            __syncthreads();                          // single sync per chunk
        }
    }

    // LSTM cell update (gate order i, f, g, o); c stays in registers
    const int u  = utile * 32 + lane;
    const int rb = btile * 64 + wrp * 8;
#pragma unroll
    for (int rr = 0; rr < 8; ++rr) {
        float gi = sumhalves(acc[rr][0]);
        float gf = sumhalves(acc[rr][1]);
        float gg = sumhalves(acc[rr][2]);
        float go = sumhalves(acc[rr][3]);
        float cc = sigmf(gf) * cst[rr] + sigmf(gi) * tanhap(gg);
        cst[rr] = cc;
        hout[(rb + rr) * 512 + u] = sigmf(go) * tanhap(cc);
    }
}

// ---------------------------------------------------------------------------
// FC tile: 64 batch x 32 cols, K = 512.  out = hin @ wfc^T + bfc
// warp w -> rows w*8..w*8+7 ; lane -> column.
// ---------------------------------------------------------------------------
__device__ __forceinline__ void fc_tile(
    const float* __restrict__ hin,   // [256,512]
    const float* __restrict__ wfc,   // [256,512]
    const float* __restrict__ bfc,
    float* __restrict__ outp, int ostride,
    int fb, int fv,
    float* smbase)
{
    const int tid = threadIdx.x, lane = tid & 31, wrp = tid >> 5;
    const int c0 = fv * 32 + lane;

    u64 acc[8];
    {
        u64 bb = pk2(bfc[c0], 0.0f);
#pragma unroll
        for (int r = 0; r < 8; ++r) acc[r] = bb;
    }

    float4 ph[2], pwf;
    auto ld = [&](int c) {
        int kc = c * 32;
#pragma unroll
        for (int q = 0; q < 2; ++q) {
            int idx = tid + q * 256, r8 = idx >> 3, kq = idx & 7;
            ph[q] = __ldcg((const float4*)(hin + (fb * 64 + r8) * 512 + kc + kq * 4));
        }
        int vv = tid >> 3, kq = tid & 7;
        pwf = __ldcg((const float4*)(wfc + (fv * 32 + vv) * 512 + kc + kq * 4));
    };
    auto stg = [&](float* buf) {
        float* sA  = buf;
        float* sWf = buf + 2304;
#pragma unroll
        for (int q = 0; q < 2; ++q) {
            int idx = tid + q * 256, r8 = idx >> 3, kq = idx & 7;
            *(float4*)(sA + r8 * 36 + kq * 4) = ph[q];
        }
        int vv = tid >> 3, kq = tid & 7;
        *(float4*)(sWf + vv * 36 + kq * 4) = pwf;
    };

    ld(0);
    stg(smbase);
    __syncthreads();

#pragma unroll 1
    for (int c = 0; c < 16; ++c) {
        const bool more = (c + 1 < 16);
        if (more) ld(c + 1);

        float* sA  = smbase + (c & 1) * CHUNK_F;
        float* sWf = sA + 2304;
#pragma unroll
        for (int kq4 = 0; kq4 < 8; ++kq4) {
            const int k = kq4 * 4;
            ulonglong2 w = *(const ulonglong2*)(sWf + lane * 36 + k);
#pragma unroll
            for (int r = 0; r < 8; ++r) {
                ulonglong2 a = *(const ulonglong2*)(sA + (wrp * 8 + r) * 36 + k);
                fma2(acc[r], a.x, w.x);
                fma2(acc[r], a.y, w.y);
            }
        }

        if (more) {
            stg(smbase + ((c + 1) & 1) * CHUNK_F);
            __syncthreads();
        }
    }

#pragma unroll
    for (int r = 0; r < 8; ++r) {
        int rr = fb * 64 + wrp * 8 + r;
        outp[rr * ostride + c0] = sumhalves(acc[r]);
    }
}

// ---------------------------------------------------------------------------
// Persistent kernel: 128 CTAs (64/direction), 512 barriers/direction.
// Phase A(t): L0-gates(t) [CTAs 0-31] || L1-gates(t-1) [CTAs 32-63]
// Phase B(t): FC0(t)                 || FC1(t-1) -> d_out
// ---------------------------------------------------------------------------
__global__ void __launch_bounds__(256, 1)
bilstm_kernel(const float* __restrict__ x,
              const float* __restrict__ wih_l, const float* __restrict__ whh_l,
              const float* __restrict__ bih_l, const float* __restrict__ bhh_l,
              const float* __restrict__ wfc_l, const float* __restrict__ bfc_l,
              const float* __restrict__ wih_r, const float* __restrict__ whh_r,
              const float* __restrict__ bih_r, const float* __restrict__ bhh_r,
              const float* __restrict__ wfc_r, const float* __restrict__ bfc_r,
              float* __restrict__ out)
{
    extern __shared__ __align__(16) float smem[];   // 2 * CHUNK_F floats

    const int dir  = (int)(blockIdx.x >> 6);
    const int r    = (int)(blockIdx.x & 63);
    const int lane = threadIdx.x & 31;

    const float* wih = dir ? wih_r : wih_l;
    const float* whh = dir ? whh_r : whh_l;
    const float* bih = dir ? bih_r : bih_l;
    const float* bhh = dir ? bhh_r : bhh_l;
    const float* wfc = dir ? wfc_r : wfc_l;
    const float* bfc = dir ? bfc_r : bfc_l;

    const bool isL0  = (r < 32);
    const int  gr    = isL0 ? r : (r - 32);
    const int  layer = isL0 ? 0 : 1;

    int bt[2], ut[2];
#pragma unroll
    for (int p = 0; p < 2; ++p) { int m = 2 * gr + p; bt[p] = m >> 4; ut[p] = m & 15; }

    const float* gwih = wih + layer * 2048 * 256;
    const float* gwhh = whh + layer * 2048 * 512;
    const float* lbih = bih + layer * 2048;
    const float* lbhh = bhh + layer * 2048;
    const float* fwfc = wfc + layer * 256 * 512;
    const float* fbfc = bfc + layer * 256;

    float gb[2][4];
#pragma unroll
    for (int p = 0; p < 2; ++p) {
        int u = ut[p] * 32 + lane;
        gb[p][0] = lbih[u]        + lbhh[u];
        gb[p][1] = lbih[512 + u]  + lbhh[512 + u];
        gb[p][2] = lbih[1024 + u] + lbhh[1024 + u];
        gb[p][3] = lbih[1536 + u] + lbhh[1536 + u];
    }
    const int fb = gr >> 3, fv = gr & 7;

    float cst[2][8];
#pragma unroll
    for (int p = 0; p < 2; ++p)
#pragma unroll
        for (int i = 0; i < 8; ++i) cst[p][i] = 0.0f;

#pragma unroll 1
    for (int t = 0; t <= 255; ++t) {
        // ---------------- Phase A: gate GEMMs + cell ----------------
        bool doG; const float* vin; int vs, nch; const float* hp; float* ho;
        if (isL0) {
            doG = (t < 255);
            int xc = dir ? (255 - t) : t;
            vin = x + xc * 256;  vs = 65536;
            nch = (t == 0) ? 8 : 24;
            hp = g_h0[dir][(t + 1) & 1];
            ho = g_h0[dir][t & 1];
        } else {
            int s = t - 1;
            doG = (s >= 0);
            vin = g_v1[dir];  vs = 256;
            nch = (s <= 0) ? 8 : 24;
            hp = g_h1[dir][(s + 1) & 1];
            ho = g_h1[dir][s & 1];
        }
        if (doG) {
#pragma unroll 1
            for (int p = 0; p < 2; ++p)
                gate_tile(vin, vs, hp, gwih, gwhh,
                          gb[p][0], gb[p][1], gb[p][2], gb[p][3],
                          ho, cst[p], bt[p], ut[p], nch, smem);
        }
        dbar(dir);

        // ---------------- Phase B: FC layers ----------------
        bool doF; const float* hin; float* op; int os;
        if (isL0) {
            doF = (t < 255);
            hin = g_h0[dir][t & 1];
            op  = g_v1[dir];  os = 256;
        } else {
            int s = t - 1;
            doF = (s >= 0);
            hin = g_h1[dir][s & 1];
            int tcol = dir ? (255 + s) : s;
            op  = out + tcol * 256;  os = 510 * 256;
        }
        if (doF) fc_tile(hin, fwfc, fbfc, op, os, fb, fv, smem);
        dbar(dir);
    }
}

extern "C" void kernel_launch(void* const* d_in, const int* in_sizes, int n_in,
                              void* d_out, int out_size)
{
    (void)in_sizes; (void)n_in; (void)out_size;
    cudaFuncSetAttribute(bilstm_kernel,
                         cudaFuncAttributeMaxDynamicSharedMemorySize, SMEM_BYTES);
    bilstm_kernel<<<128, 256, SMEM_BYTES>>>(
        (const float*)d_in[0],
        (const float*)d_in[1],  (const float*)d_in[2],  (const float*)d_in[3],
        (const float*)d_in[4],  (const float*)d_in[5],  (const float*)d_in[6],
        (const float*)d_in[7],  (const float*)d_in[8],  (const float*)d_in[9],
        (const float*)d_in[10], (const float*)d_in[11], (const float*)d_in[12],
        (float*)d_out);
}